// round 13
// baseline (speedup 1.0000x reference)
#include <cuda_runtime.h>
#include <cuda_fp16.h>
#include <math.h>
#include <cstdint>

#define Bsz 64
#define Tq  77
#define Dm  256
#define Hh  8
#define DFFm 2048
#define Mem 800

// ---------------- scratch ----------------
__device__ float g_qkv [Bsz*Tq*768];
__device__ float g_attn[Bsz*Tq*Dm];
__device__ float g_proj[Bsz*Tq*Dm];
__device__ float g_x1  [Bsz*Tq*Dm];
__device__ float g_x2  [Bsz*Tq*Dm];
__device__ float g_caq [Bsz*Tq*Dm];
__device__ float g_cakv[Bsz*Mem*512];
__device__ float g_ffh [(size_t)Bsz*Tq*DFFm];

__device__ __forceinline__ void mma_f16(float* d, const uint32_t* a, const uint32_t* b) {
    asm volatile("mma.sync.aligned.m16n8k16.row.col.f32.f16.f16.f32 "
        "{%0,%1,%2,%3}, {%4,%5,%6,%7}, {%8,%9}, {%0,%1,%2,%3};"
        : "+f"(d[0]), "+f"(d[1]), "+f"(d[2]), "+f"(d[3])
        : "r"(a[0]), "r"(a[1]), "r"(a[2]), "r"(a[3]), "r"(b[0]), "r"(b[1]));
}
__device__ __forceinline__ uint32_t h2u(__half2 h) { return *reinterpret_cast<uint32_t*>(&h); }
__device__ __forceinline__ uint32_t pk2(float2 v) { return h2u(__floats2half2_rn(v.x, v.y)); }
__device__ __forceinline__ uint32_t su32(const void* p) {
    uint32_t a;
    asm("{ .reg .u64 t; cvta.to.shared.u64 t, %1; cvt.u32.u64 %0, t; }" : "=r"(a) : "l"(p));
    return a;
}
#define CP16(dst, src, sz) \
    asm volatile("cp.async.ca.shared.global [%0], [%1], 16, %2;" :: "r"(dst), "l"(src), "r"(sz))
#define CP16U(dst, src) \
    asm volatile("cp.async.ca.shared.global [%0], [%1], 16;" :: "r"(dst), "l"(src))
#define CPCOMMIT() asm volatile("cp.async.commit_group;" ::: "memory")
#define CPWAIT2()  asm volatile("cp.async.wait_group 2;" ::: "memory")

// ======== fp16 mma GEMM, cp.async 4-stage f32 pipeline ========
// CTA 128Mx128N, BK=32/stage, 4 stages (3 chunks always in flight).
// 512 threads / 16 warps as 4(M)x4(N), warp tile 32x32.
// smem f32, fragments built via ld.shared.v2.f32 + cvt (layout == proven R5 map).
#define SPITCH 40
#define SSTG   (128 * SPITCH)                 // floats per stage per array
#define GSM    (4 * 2 * SSTG * 4)             // 163840 bytes

template<bool RELU>
__global__ void __launch_bounds__(512, 1) gemm_h(
    const float* __restrict__ A1, const float* __restrict__ A2, int msplit, long a_bs,
    const float* __restrict__ Wbank, long w_bs, int w_roff,
    const float* __restrict__ Bbank, long b_bs, const int* __restrict__ sid,
    float* __restrict__ C, long c_bs, int M, int Nn, int K)
{
    extern __shared__ float fsm[];
    // A stages: fsm + s*SSTG ; W stages: fsm + 4*SSTG + s*SSTG

    const int tid = threadIdx.x, wid = tid >> 5, lane = tid & 31;
    const int b = blockIdx.z, s = sid[b];
    const int m0 = blockIdx.y * 128, n0 = blockIdx.x * 128;
    const float* W  = Wbank + (long)s * w_bs + (long)w_roff * K;
    const float* Bi = Bbank + (long)s * b_bs + w_roff;
    const int NC = K >> 5;
    const int wm = (wid >> 2) * 32, wn = (wid & 3) * 32;
    const int g = lane >> 2, t4 = lane & 3;
    const int lr = g, lc = t4;

    float acc[2][4][4];
    #pragma unroll
    for (int i = 0; i < 2; i++)
        #pragma unroll
        for (int j = 0; j < 4; j++)
            #pragma unroll
            for (int r = 0; r < 4; r++) acc[i][j][r] = 0.f;

    // cp.async issue for chunk c into stage c&3 (4 transfers per thread)
    auto issue = [&](int c) {
        const int st = c & 3;
        const int k0 = c << 5;
        #pragma unroll
        for (int r = 0; r < 2; r++) {
            int idx = tid + (r << 9);
            int row = idx >> 3, c4 = idx & 7;
            uint32_t dst = su32(&fsm[st * SSTG + row * SPITCH + (c4 << 2)]);
            int rg = m0 + row;
            const float* src = A1;
            uint32_t sz = 0;
            if (rg < M) {
                src = ((rg < msplit)
                    ? (A1 + (long)b * a_bs + (long)rg * K)
                    : (A2 + (long)b * a_bs + (long)(rg - msplit) * K)) + k0 + (c4 << 2);
                sz = 16;
            }
            CP16(dst, src, sz);
        }
        #pragma unroll
        for (int r = 0; r < 2; r++) {
            int idx = tid + (r << 9);
            int row = idx >> 3, c4 = idx & 7;
            uint32_t dst = su32(&fsm[4 * SSTG + st * SSTG + row * SPITCH + (c4 << 2)]);
            CP16U(dst, W + (long)(n0 + row) * K + k0 + (c4 << 2));
        }
    };

    issue(0); CPCOMMIT();
    issue(1); CPCOMMIT();
    issue(2); CPCOMMIT();

    for (int c = 0; c < NC; c++) {
        CPWAIT2();
        __syncthreads();
        if (c + 3 < NC) issue(c + 3);
        CPCOMMIT();

        const float* As = fsm + (c & 3) * SSTG;
        const float* Ws = fsm + 4 * SSTG + (c & 3) * SSTG;
        #pragma unroll
        for (int ks = 0; ks < 2; ks++) {
            const int kc = ks * 16 + 2 * t4;
            uint32_t af[2][4], bf[4][2];
            #pragma unroll
            for (int mf = 0; mf < 2; mf++) {
                const float* ar0 = As + (wm + mf * 16 + g) * SPITCH + kc;
                const float* ar1 = ar0 + 8 * SPITCH;
                af[mf][0] = pk2(*reinterpret_cast<const float2*>(ar0));
                af[mf][1] = pk2(*reinterpret_cast<const float2*>(ar1));
                af[mf][2] = pk2(*reinterpret_cast<const float2*>(ar0 + 8));
                af[mf][3] = pk2(*reinterpret_cast<const float2*>(ar1 + 8));
            }
            #pragma unroll
            for (int nf = 0; nf < 4; nf++) {
                const float* wr = Ws + (wn + nf * 8 + g) * SPITCH + kc;
                bf[nf][0] = pk2(*reinterpret_cast<const float2*>(wr));
                bf[nf][1] = pk2(*reinterpret_cast<const float2*>(wr + 8));
            }
            #pragma unroll
            for (int mf = 0; mf < 2; mf++)
                #pragma unroll
                for (int nf = 0; nf < 4; nf++)
                    mma_f16(acc[mf][nf], af[mf], bf[nf]);
        }
    }

    #pragma unroll
    for (int mf = 0; mf < 2; mf++) {
        const int row = m0 + wm + mf * 16 + lr;
        #pragma unroll
        for (int nf = 0; nf < 4; nf++) {
            const int col = n0 + wn + nf * 8 + 2 * lc;
            float b0 = Bi[col], b1 = Bi[col + 1];
            if (row < M) {
                float v0 = acc[mf][nf][0] + b0;
                float v1 = acc[mf][nf][1] + b1;
                if (RELU) { v0 = fmaxf(v0, 0.f); v1 = fmaxf(v1, 0.f); }
                *reinterpret_cast<float2*>(C + (long)b * c_bs + (long)row * Nn + col) = make_float2(v0, v1);
            }
            if (row + 8 < M) {
                float v2 = acc[mf][nf][2] + b0;
                float v3 = acc[mf][nf][3] + b1;
                if (RELU) { v2 = fmaxf(v2, 0.f); v3 = fmaxf(v3, 0.f); }
                *reinterpret_cast<float2*>(C + (long)b * c_bs + (long)(row + 8) * Nn + col) = make_float2(v2, v3);
            }
        }
    }
}

// ======== tensor-core flash attention (unchanged) ========
#define AO_Q   0
#define AO_K   6400
#define AO_V   11520
#define AO_P   16128
#define AO_S   27648
#define AO_F   49088
#define AO_L   49408
#define AO_M   49728
#define AO_SZ  49920

__global__ void __launch_bounds__(128) attn_tc(
    const float* __restrict__ Q, int q_rs, long q_bs,
    const float* __restrict__ Kp, int k_rs, long k_bs,
    const float* __restrict__ Vp, int v_rs, long v_bs,
    const unsigned char* __restrict__ m1, int m1_bs,
    const unsigned char* __restrict__ m2, int m2_bs, int msplit,
    int nk, float* __restrict__ O)
{
    extern __shared__ char sm[];
    uint32_t* Q16 = (uint32_t*)(sm + AO_Q);
    uint32_t* K16 = (uint32_t*)(sm + AO_K);
    uint32_t* Vt  = (uint32_t*)(sm + AO_V);
    __half*   Vth = (__half*)(sm + AO_V);
    uint32_t* Pf  = (uint32_t*)(sm + AO_P);
    float*    Sf  = (float*)(sm + AO_S);
    float*    rowf= (float*)(sm + AO_F);
    float*    linv= (float*)(sm + AO_L);
    unsigned char* mk = (unsigned char*)(sm + AO_M);

    const int h = blockIdx.x, b = blockIdx.y;
    const int tid = threadIdx.x, wid = tid >> 5;
    const int g = (tid & 31) >> 2, t4 = tid & 3;
    const float* Qb = Q  + (long)b * q_bs + h * 32;
    const float* Kb = Kp + (long)b * k_bs + h * 32;
    const float* Vb = Vp + (long)b * v_bs + h * 32;
    const int NCH = (nk + 63) >> 6;
    const float scl = 0.17677669529663687f;

    for (int i = tid; i < 80 * 8; i += 128) {
        int row = i >> 3, c4 = i & 7;
        float4 v = make_float4(0.f, 0.f, 0.f, 0.f);
        if (row < Tq) v = *reinterpret_cast<const float4*>(Qb + (long)row * q_rs + (c4 << 2));
        uint2 u = make_uint2(h2u(__floats2half2_rn(v.x * scl, v.y * scl)),
                             h2u(__floats2half2_rn(v.z * scl, v.w * scl)));
        *reinterpret_cast<uint2*>(&Q16[row * 20 + 2 * c4]) = u;
    }

    float mrow = -INFINITY, lrow = 0.f;
    const int mfcnt = (wid == 3) ? 2 : 1;
    const int mrow0 = wid * 16;
    float acc[2][4][4];
    #pragma unroll
    for (int i = 0; i < 2; i++)
        #pragma unroll
        for (int j = 0; j < 4; j++)
            #pragma unroll
            for (int r = 0; r < 4; r++) acc[i][j][r] = 0.f;

    for (int c = 0; c < NCH; c++) {
        const int j0 = c << 6;
        __syncthreads();
        for (int i = tid; i < 64 * 8; i += 128) {
            int key = i >> 3, c4 = i & 7;
            int j = j0 + key;
            float4 kv = make_float4(0.f, 0.f, 0.f, 0.f);
            float4 vv = make_float4(0.f, 0.f, 0.f, 0.f);
            if (j < nk) {
                kv = *reinterpret_cast<const float4*>(Kb + (long)j * k_rs + (c4 << 2));
                vv = *reinterpret_cast<const float4*>(Vb + (long)j * v_rs + (c4 << 2));
            }
            uint2 u = make_uint2(h2u(__floats2half2_rn(kv.x, kv.y)),
                                 h2u(__floats2half2_rn(kv.z, kv.w)));
            *reinterpret_cast<uint2*>(&K16[key * 20 + 2 * c4]) = u;
            int d0 = c4 << 2;
            Vth[(d0    ) * 72 + key] = __float2half(vv.x);
            Vth[(d0 + 1) * 72 + key] = __float2half(vv.y);
            Vth[(d0 + 2) * 72 + key] = __float2half(vv.z);
            Vth[(d0 + 3) * 72 + key] = __float2half(vv.w);
        }
        if (tid < 64) {
            int j = j0 + tid;
            mk[tid] = (j >= nk) ? 2
                    : ((j < msplit) ? m1[(long)b * m1_bs + j]
                                    : m2[(long)b * m2_bs + j - msplit]);
        }
        __syncthreads();
        {
            float sacc[5][2][4];
            #pragma unroll
            for (int mf = 0; mf < 5; mf++)
                #pragma unroll
                for (int nf = 0; nf < 2; nf++)
                    #pragma unroll
                    for (int r = 0; r < 4; r++) sacc[mf][nf][r] = 0.f;
            #pragma unroll
            for (int ks = 0; ks < 2; ks++) {
                uint32_t af[5][4];
                #pragma unroll
                for (int mf = 0; mf < 5; mf++) {
                    const uint32_t* ap = &Q16[(mf * 16 + g) * 20 + ks * 8 + t4];
                    af[mf][0] = ap[0]; af[mf][1] = ap[8 * 20];
                    af[mf][2] = ap[4]; af[mf][3] = ap[8 * 20 + 4];
                }
                #pragma unroll
                for (int nf = 0; nf < 2; nf++) {
                    const uint32_t* wp = &K16[(wid * 16 + nf * 8 + g) * 20 + ks * 8 + t4];
                    uint32_t bf[2] = { wp[0], wp[4] };
                    #pragma unroll
                    for (int mf = 0; mf < 5; mf++) mma_f16(sacc[mf][nf], af[mf], bf);
                }
            }
            #pragma unroll
            for (int mf = 0; mf < 5; mf++) {
                #pragma unroll
                for (int nf = 0; nf < 2; nf++) {
                    int r0 = mf * 16 + g, col = wid * 16 + nf * 8 + 2 * t4;
                    Sf[r0 * 67 + col]       = sacc[mf][nf][0];
                    Sf[r0 * 67 + col + 1]   = sacc[mf][nf][1];
                    Sf[(r0+8) * 67 + col]   = sacc[mf][nf][2];
                    Sf[(r0+8) * 67 + col+1] = sacc[mf][nf][3];
                }
            }
        }
        __syncthreads();
        if (tid < 80) {
            float* srow = Sf + tid * 67;
            float cmax = -3.0e38f;
            for (int k = 0; k < 64; k++) {
                float sv = srow[k];
                unsigned char mv = mk[k];
                if (mv) sv = (mv == 1) ? -1e9f : -2e9f;
                srow[k] = sv;
                cmax = fmaxf(cmax, sv);
            }
            float newm = fmaxf(mrow, cmax);
            float f = __expf(mrow - newm);
            float sum = 0.f;
            uint32_t* prow = Pf + tid * 36;
            for (int k2 = 0; k2 < 32; k2++) {
                float p0 = __expf(srow[2*k2]   - newm);
                float p1 = __expf(srow[2*k2+1] - newm);
                sum += p0 + p1;
                prow[k2] = h2u(__floats2half2_rn(p0, p1));
            }
            lrow = lrow * f + sum;
            rowf[tid] = f;
            mrow = newm;
        }
        __syncthreads();
        #pragma unroll
        for (int mi = 0; mi < 2; mi++) {
            if (mi >= mfcnt) break;
            int rb = mrow0 + mi * 16;
            float f0 = rowf[rb + g], f1 = rowf[rb + 8 + g];
            #pragma unroll
            for (int nf = 0; nf < 4; nf++) {
                acc[mi][nf][0] *= f0; acc[mi][nf][1] *= f0;
                acc[mi][nf][2] *= f1; acc[mi][nf][3] *= f1;
            }
        }
        #pragma unroll
        for (int kf = 0; kf < 4; kf++) {
            uint32_t af[2][4];
            #pragma unroll
            for (int mi = 0; mi < 2; mi++) {
                if (mi >= mfcnt) break;
                const uint32_t* ap = &Pf[(mrow0 + mi * 16 + g) * 36 + kf * 8 + t4];
                af[mi][0] = ap[0]; af[mi][1] = ap[8 * 36];
                af[mi][2] = ap[4]; af[mi][3] = ap[8 * 36 + 4];
            }
            #pragma unroll
            for (int nf = 0; nf < 4; nf++) {
                const uint32_t* bp = &Vt[(nf * 8 + g) * 36 + kf * 8 + t4];
                uint32_t bf[2] = { bp[0], bp[4] };
                #pragma unroll
                for (int mi = 0; mi < 2; mi++) {
                    if (mi >= mfcnt) break;
                    mma_f16(acc[mi][nf], af[mi], bf);
                }
            }
        }
    }

    if (tid < 80) linv[tid] = 1.f / lrow;
    __syncthreads();

    #pragma unroll
    for (int mi = 0; mi < 2; mi++) {
        if (mi >= mfcnt) break;
        int rb = mrow0 + mi * 16;
        int r0 = rb + g, r1 = rb + 8 + g;
        float i0 = linv[r0], i1 = linv[r1];
        #pragma unroll
        for (int nf = 0; nf < 4; nf++) {
            int col = h * 32 + nf * 8 + 2 * t4;
            if (r0 < Tq)
                *reinterpret_cast<float2*>(O + ((long)b * Tq + r0) * Dm + col)
                    = make_float2(acc[mi][nf][0] * i0, acc[mi][nf][1] * i0);
            if (r1 < Tq)
                *reinterpret_cast<float2*>(O + ((long)b * Tq + r1) * Dm + col)
                    = make_float2(acc[mi][nf][2] * i1, acc[mi][nf][3] * i1);
        }
    }
}

// ---------------- residual + layernorm ----------------
__global__ void resid_ln(const float* __restrict__ X, const float* __restrict__ Y,
                         const float* __restrict__ Wb, const float* __restrict__ Bb,
                         const int* __restrict__ sid, float* __restrict__ Out)
{
    const int row = blockIdx.x;
    const int b = row / Tq;
    const int i = threadIdx.x;
    const int s = sid[b];
    float v = X[(long)row * Dm + i] + Y[(long)row * Dm + i];

    float sum = v, sq = v * v;
    #pragma unroll
    for (int off = 16; off > 0; off >>= 1) {
        sum += __shfl_xor_sync(0xffffffffu, sum, off);
        sq  += __shfl_xor_sync(0xffffffffu, sq,  off);
    }
    __shared__ float sS[8], sQ[8];
    if ((i & 31) == 0) { sS[i >> 5] = sum; sQ[i >> 5] = sq; }
    __syncthreads();
    float ts = 0.f, tq = 0.f;
    #pragma unroll
    for (int k = 0; k < 8; k++) { ts += sS[k]; tq += sQ[k]; }

    float mean = ts * (1.f / 256.f);
    float var  = tq * (1.f / 256.f) - mean * mean;
    float rstd = rsqrtf(var + 1e-5f);
    Out[(long)row * Dm + i] = (v - mean) * rstd * Wb[(long)s * Dm + i] + Bb[(long)s * Dm + i];
}

// ---------------------------------- launch ---------------------------------------------
extern "C" void kernel_launch(void* const* d_in, const int* in_sizes, int n_in,
                              void* d_out, int out_size)
{
    const float*         text  = (const float*)d_in[0];
    const unsigned char* tmask = (const unsigned char*)d_in[1];
    const float*         im1   = (const float*)d_in[2];
    const unsigned char* imk1  = (const unsigned char*)d_in[3];
    const float*         im2   = (const float*)d_in[4];
    const unsigned char* imk2  = (const unsigned char*)d_in[5];
    const int*           sid   = (const int*)d_in[6];
    const float* sa_in_w  = (const float*)d_in[7];
    const float* sa_in_b  = (const float*)d_in[8];
    const float* sa_out_w = (const float*)d_in[9];
    const float* sa_out_b = (const float*)d_in[10];
    const float* ca_in_w  = (const float*)d_in[11];
    const float* ca_in_b  = (const float*)d_in[12];
    const float* ca_out_w = (const float*)d_in[13];
    const float* ca_out_b = (const float*)d_in[14];
    const float* l1w = (const float*)d_in[15];
    const float* l1b = (const float*)d_in[16];
    const float* l2w = (const float*)d_in[17];
    const float* l2b = (const float*)d_in[18];
    const float* n1w = (const float*)d_in[19];
    const float* n1b = (const float*)d_in[20];
    const float* n2w = (const float*)d_in[21];
    const float* n2b = (const float*)d_in[22];
    const float* n3w = (const float*)d_in[23];
    const float* n3b = (const float*)d_in[24];
    float* out = (float*)d_out;

    static float *qkv=nullptr,*attn=nullptr,*proj=nullptr,*x1=nullptr,*x2=nullptr,
                 *caq=nullptr,*cakv=nullptr,*ffh=nullptr;
    static cudaStream_t s2 = nullptr;
    static cudaEvent_t evFork = nullptr, evJoin = nullptr;
    if (!qkv) {
        cudaGetSymbolAddress((void**)&qkv,  g_qkv);
        cudaGetSymbolAddress((void**)&attn, g_attn);
        cudaGetSymbolAddress((void**)&proj, g_proj);
        cudaGetSymbolAddress((void**)&x1,   g_x1);
        cudaGetSymbolAddress((void**)&x2,   g_x2);
        cudaGetSymbolAddress((void**)&caq,  g_caq);
        cudaGetSymbolAddress((void**)&cakv, g_cakv);
        cudaGetSymbolAddress((void**)&ffh,  g_ffh);
        cudaFuncSetAttribute(attn_tc, cudaFuncAttributeMaxDynamicSharedMemorySize, AO_SZ);
        cudaFuncSetAttribute(gemm_h<false>, cudaFuncAttributeMaxDynamicSharedMemorySize, GSM);
        cudaFuncSetAttribute(gemm_h<true>,  cudaFuncAttributeMaxDynamicSharedMemorySize, GSM);
        cudaStreamCreateWithFlags(&s2, cudaStreamNonBlocking);
        cudaEventCreateWithFlags(&evFork, cudaEventDisableTiming);
        cudaEventCreateWithFlags(&evJoin, cudaEventDisableTiming);
    }

    const int LNROWS = Bsz * Tq;

    // ---- fork: CA K/V projection concurrent with SA chain ----
    cudaEventRecord(evFork, 0);
    cudaStreamWaitEvent(s2, evFork, 0);

    // [s2] 6) CA key/value proj from concat(im1,im2): M=800 -> 7 tiles of 128
    gemm_h<false><<<dim3(512/128, 7, Bsz), 512, GSM, s2>>>(
        im1, im2, 400, (long)400*Dm,
        ca_in_w, (long)768*Dm, 256, ca_in_b, 768, sid,
        cakv, (long)Mem*512, Mem, 512, Dm);
    cudaEventRecord(evJoin, s2);

    // [main] 1) SA qkv projection
    gemm_h<false><<<dim3(768/128, 1, Bsz), 512, GSM>>>(
        text, text, Tq, (long)Tq*Dm,
        sa_in_w, (long)768*Dm, 0, sa_in_b, 768, sid,
        qkv, (long)Tq*768, Tq, 768, Dm);

    // [main] 2) SA attention
    attn_tc<<<dim3(Hh, Bsz), 128, AO_SZ>>>(
        qkv,       768, (long)Tq*768,
        qkv + 256, 768, (long)Tq*768,
        qkv + 512, 768, (long)Tq*768,
        tmask, Tq, tmask, 0, Tq + 1,
        Tq, attn);

    // [main] 3) SA out proj
    gemm_h<false><<<dim3(Dm/128, 1, Bsz), 512, GSM>>>(
        attn, attn, Tq, (long)Tq*Dm,
        sa_out_w, (long)Dm*Dm, 0, sa_out_b, Dm, sid,
        proj, (long)Tq*Dm, Tq, Dm, Dm);

    // [main] 4) residual + LN1 -> x1
    resid_ln<<<LNROWS, 256>>>(text, proj, n1w, n1b, sid, x1);

    // [main] 5) CA query proj
    gemm_h<false><<<dim3(Dm/128, 1, Bsz), 512, GSM>>>(
        x1, x1, Tq, (long)Tq*Dm,
        ca_in_w, (long)768*Dm, 0, ca_in_b, 768, sid,
        caq, (long)Tq*Dm, Tq, Dm, Dm);

    // ---- join ----
    cudaStreamWaitEvent(0, evJoin, 0);

    // 7) CA attention
    attn_tc<<<dim3(Hh, Bsz), 128, AO_SZ>>>(
        caq,        Dm,  (long)Tq*Dm,
        cakv,       512, (long)Mem*512,
        cakv + 256, 512, (long)Mem*512,
        imk1, 400, imk2, 400, 400,
        Mem, attn);

    // 8) CA out proj
    gemm_h<false><<<dim3(Dm/128, 1, Bsz), 512, GSM>>>(
        attn, attn, Tq, (long)Tq*Dm,
        ca_out_w, (long)Dm*Dm, 0, ca_out_b, Dm, sid,
        proj, (long)Tq*Dm, Tq, Dm, Dm);

    // 9) residual + LN2 -> x2
    resid_ln<<<LNROWS, 256>>>(x1, proj, n2w, n2b, sid, x2);

    // 10) FFN up + relu
    gemm_h<true><<<dim3(DFFm/128, 1, Bsz), 512, GSM>>>(
        x2, x2, Tq, (long)Tq*Dm,
        l1w, (long)DFFm*Dm, 0, l1b, DFFm, sid,
        ffh, (long)Tq*DFFm, Tq, DFFm, Dm);

    // 11) FFN down
    gemm_h<false><<<dim3(Dm/128, 1, Bsz), 512, GSM>>>(
        ffh, ffh, Tq, (long)Tq*DFFm,
        l2w, (long)Dm*DFFm, 0, l2b, Dm, sid,
        proj, (long)Tq*Dm, Tq, Dm, DFFm);

    // 12) residual + LN3 -> output
    resid_ln<<<LNROWS, 256>>>(x2, proj, n3w, n3b, sid, out);
}

// round 14
// speedup vs baseline: 1.2487x; 1.2487x over previous
#include <cuda_runtime.h>
#include <cuda_fp16.h>
#include <math.h>
#include <cstdint>

#define Bsz 64
#define Tq  77
#define Dm  256
#define Hh  8
#define DFFm 2048
#define Mem 800

// ---------------- scratch ----------------
__device__ float g_qkv [Bsz*Tq*768];
__device__ float g_attn[Bsz*Tq*Dm];
__device__ float g_proj[Bsz*Tq*Dm];
__device__ float g_x1  [Bsz*Tq*Dm];
__device__ float g_x2  [Bsz*Tq*Dm];
__device__ float g_caq [Bsz*Tq*Dm];
__device__ float g_cakv[Bsz*Mem*512];
__device__ float g_ffh [(size_t)Bsz*Tq*DFFm];
__device__ int   g_perm[Bsz];

__device__ __forceinline__ void mma_f16(float* d, const uint32_t* a, const uint32_t* b) {
    asm volatile("mma.sync.aligned.m16n8k16.row.col.f32.f16.f16.f32 "
        "{%0,%1,%2,%3}, {%4,%5,%6,%7}, {%8,%9}, {%0,%1,%2,%3};"
        : "+f"(d[0]), "+f"(d[1]), "+f"(d[2]), "+f"(d[3])
        : "r"(a[0]), "r"(a[1]), "r"(a[2]), "r"(a[3]), "r"(b[0]), "r"(b[1]));
}
__device__ __forceinline__ uint32_t h2u(__half2 h) { return *reinterpret_cast<uint32_t*>(&h); }
__device__ __forceinline__ uint32_t su32(const void* p) {
    uint32_t a;
    asm("{ .reg .u64 t; cvta.to.shared.u64 t, %1; cvt.u32.u64 %0, t; }" : "=r"(a) : "l"(p));
    return a;
}
__device__ __forceinline__ void ldsm_x4(uint32_t* r, uint32_t addr) {
    asm volatile("ldmatrix.sync.aligned.m8n8.x4.shared.b16 {%0,%1,%2,%3}, [%4];"
        : "=r"(r[0]), "=r"(r[1]), "=r"(r[2]), "=r"(r[3]) : "r"(addr));
}

// ---- sid rank-sort: perm[rank] = batch, equal sids adjacent ----
__global__ void sid_sort(const int* __restrict__ sid, int* __restrict__ perm) {
    int i = threadIdx.x;
    if (i < Bsz) {
        int si = sid[i];
        int rank = 0;
        for (int j = 0; j < Bsz; j++) {
            int sj = sid[j];
            if (sj < si || (sj == si && j < i)) rank++;
        }
        perm[rank] = i;
    }
}

// ======== fp16 mma GEMM (R10 config): C[b] = A[b] @ W[sid[b]]^T + bias ========
// CTA 128Mx128N, BK=64. 8 warps 2(M)x4(N), warp tile 64x32.
// 16 float4 staged per thread; batch taken from perm[blockIdx.z].
#define GPITCH 36
#define GBUF   (128 * GPITCH)
#define GSM    (2 * GBUF * 4 * 2)      // 73728 bytes

template<bool RELU>
__global__ void __launch_bounds__(256) gemm_h(
    const float* __restrict__ A1, const float* __restrict__ A2, int msplit, long a_bs,
    const float* __restrict__ Wbank, long w_bs, int w_roff,
    const float* __restrict__ Bbank, long b_bs, const int* __restrict__ sid,
    const int* __restrict__ perm,
    float* __restrict__ C, long c_bs, int M, int Nn, int K)
{
    extern __shared__ uint32_t dyn[];
    uint32_t* Abuf = dyn;
    uint32_t* Wbuf = dyn + 2 * GBUF;

    const int tid = threadIdx.x, wid = tid >> 5, lane = tid & 31;
    const int b = perm[blockIdx.z], s = sid[b];
    const int m0 = blockIdx.y * 128, n0 = blockIdx.x * 128;
    const float* W  = Wbank + (long)s * w_bs + (long)w_roff * K;
    const float* Bi = Bbank + (long)s * b_bs + w_roff;
    const int NC = K >> 6;
    const int wm = (wid >> 2) * 64, wn = (wid & 3) * 32;
    const int lr = lane >> 2, lc = lane & 3;
    const int la7 = lane & 7, la15 = lane & 15;
    const int acol = (lane >> 4) * 4;
    const int brow = (lane >> 4) * 8 + la7;
    const int bcol = ((lane >> 3) & 1) * 4;

    float acc[4][4][4];
    #pragma unroll
    for (int i = 0; i < 4; i++)
        #pragma unroll
        for (int j = 0; j < 4; j++)
            #pragma unroll
            for (int r = 0; r < 4; r++) acc[i][j][r] = 0.f;

    const int sr = tid >> 4, sc4 = tid & 15;
    float4 areg[8], wreg[8];
    auto ldg = [&](int c) {
        const int k0 = c << 6;
        #pragma unroll
        for (int r = 0; r < 8; r++) {
            int rg = m0 + sr + r * 16;
            if (rg < M) {
                const float* Ap = (rg < msplit)
                    ? (A1 + (long)b * a_bs + (long)rg * K)
                    : (A2 + (long)b * a_bs + (long)(rg - msplit) * K);
                areg[r] = *reinterpret_cast<const float4*>(Ap + k0 + (sc4 << 2));
            } else areg[r] = make_float4(0.f, 0.f, 0.f, 0.f);
            wreg[r] = *reinterpret_cast<const float4*>(W + (long)(n0 + sr + r * 16) * K + k0 + (sc4 << 2));
        }
    };
    auto sts = [&](int p) {
        #pragma unroll
        for (int r = 0; r < 8; r++) {
            int row = sr + r * 16;
            uint2 ua = make_uint2(h2u(__floats2half2_rn(areg[r].x, areg[r].y)),
                                  h2u(__floats2half2_rn(areg[r].z, areg[r].w)));
            *reinterpret_cast<uint2*>(&Abuf[(p * 128 + row) * GPITCH + 2 * sc4]) = ua;
            uint2 uw = make_uint2(h2u(__floats2half2_rn(wreg[r].x, wreg[r].y)),
                                  h2u(__floats2half2_rn(wreg[r].z, wreg[r].w)));
            *reinterpret_cast<uint2*>(&Wbuf[(p * 128 + row) * GPITCH + 2 * sc4]) = uw;
        }
    };

    ldg(0);
    for (int c = 0; c < NC; c++) {
        const int p = c & 1;
        sts(p);
        if (c + 1 < NC) ldg(c + 1);
        __syncthreads();
        #pragma unroll
        for (int ks = 0; ks < 4; ks++) {
            uint32_t af[4][4], bf[8];
            #pragma unroll
            for (int mf = 0; mf < 4; mf++)
                ldsm_x4(af[mf], su32(&Abuf[(p * 128 + wm + mf * 16 + la15) * GPITCH + ks * 8 + acol]));
            ldsm_x4(bf,     su32(&Wbuf[(p * 128 + wn      + brow) * GPITCH + ks * 8 + bcol]));
            ldsm_x4(bf + 4, su32(&Wbuf[(p * 128 + wn + 16 + brow) * GPITCH + ks * 8 + bcol]));
            #pragma unroll
            for (int mf = 0; mf < 4; mf++)
                #pragma unroll
                for (int nf = 0; nf < 4; nf++)
                    mma_f16(acc[mf][nf], af[mf], &bf[nf * 2]);
        }
    }

    #pragma unroll
    for (int mf = 0; mf < 4; mf++) {
        const int row = m0 + wm + mf * 16 + lr;
        #pragma unroll
        for (int nf = 0; nf < 4; nf++) {
            const int col = n0 + wn + nf * 8 + 2 * lc;
            float b0 = Bi[col], b1 = Bi[col + 1];
            if (row < M) {
                float v0 = acc[mf][nf][0] + b0;
                float v1 = acc[mf][nf][1] + b1;
                if (RELU) { v0 = fmaxf(v0, 0.f); v1 = fmaxf(v1, 0.f); }
                *reinterpret_cast<float2*>(C + (long)b * c_bs + (long)row * Nn + col) = make_float2(v0, v1);
            }
            if (row + 8 < M) {
                float v2 = acc[mf][nf][2] + b0;
                float v3 = acc[mf][nf][3] + b1;
                if (RELU) { v2 = fmaxf(v2, 0.f); v3 = fmaxf(v3, 0.f); }
                *reinterpret_cast<float2*>(C + (long)b * c_bs + (long)(row + 8) * Nn + col) = make_float2(v2, v3);
            }
        }
    }
}

// ======== tensor-core flash attention (unchanged) ========
#define AO_Q   0
#define AO_K   6400
#define AO_V   11520
#define AO_P   16128
#define AO_S   27648
#define AO_F   49088
#define AO_L   49408
#define AO_M   49728
#define AO_SZ  49920

__global__ void __launch_bounds__(128) attn_tc(
    const float* __restrict__ Q, int q_rs, long q_bs,
    const float* __restrict__ Kp, int k_rs, long k_bs,
    const float* __restrict__ Vp, int v_rs, long v_bs,
    const unsigned char* __restrict__ m1, int m1_bs,
    const unsigned char* __restrict__ m2, int m2_bs, int msplit,
    int nk, float* __restrict__ O)
{
    extern __shared__ char sm[];
    uint32_t* Q16 = (uint32_t*)(sm + AO_Q);
    uint32_t* K16 = (uint32_t*)(sm + AO_K);
    uint32_t* Vt  = (uint32_t*)(sm + AO_V);
    __half*   Vth = (__half*)(sm + AO_V);
    uint32_t* Pf  = (uint32_t*)(sm + AO_P);
    float*    Sf  = (float*)(sm + AO_S);
    float*    rowf= (float*)(sm + AO_F);
    float*    linv= (float*)(sm + AO_L);
    unsigned char* mk = (unsigned char*)(sm + AO_M);

    const int h = blockIdx.x, b = blockIdx.y;
    const int tid = threadIdx.x, wid = tid >> 5;
    const int g = (tid & 31) >> 2, t4 = tid & 3;
    const float* Qb = Q  + (long)b * q_bs + h * 32;
    const float* Kb = Kp + (long)b * k_bs + h * 32;
    const float* Vb = Vp + (long)b * v_bs + h * 32;
    const int NCH = (nk + 63) >> 6;
    const float scl = 0.17677669529663687f;

    for (int i = tid; i < 80 * 8; i += 128) {
        int row = i >> 3, c4 = i & 7;
        float4 v = make_float4(0.f, 0.f, 0.f, 0.f);
        if (row < Tq) v = *reinterpret_cast<const float4*>(Qb + (long)row * q_rs + (c4 << 2));
        uint2 u = make_uint2(h2u(__floats2half2_rn(v.x * scl, v.y * scl)),
                             h2u(__floats2half2_rn(v.z * scl, v.w * scl)));
        *reinterpret_cast<uint2*>(&Q16[row * 20 + 2 * c4]) = u;
    }

    float mrow = -INFINITY, lrow = 0.f;
    const int mfcnt = (wid == 3) ? 2 : 1;
    const int mrow0 = wid * 16;
    float acc[2][4][4];
    #pragma unroll
    for (int i = 0; i < 2; i++)
        #pragma unroll
        for (int j = 0; j < 4; j++)
            #pragma unroll
            for (int r = 0; r < 4; r++) acc[i][j][r] = 0.f;

    for (int c = 0; c < NCH; c++) {
        const int j0 = c << 6;
        __syncthreads();
        for (int i = tid; i < 64 * 8; i += 128) {
            int key = i >> 3, c4 = i & 7;
            int j = j0 + key;
            float4 kv = make_float4(0.f, 0.f, 0.f, 0.f);
            float4 vv = make_float4(0.f, 0.f, 0.f, 0.f);
            if (j < nk) {
                kv = *reinterpret_cast<const float4*>(Kb + (long)j * k_rs + (c4 << 2));
                vv = *reinterpret_cast<const float4*>(Vb + (long)j * v_rs + (c4 << 2));
            }
            uint2 u = make_uint2(h2u(__floats2half2_rn(kv.x, kv.y)),
                                 h2u(__floats2half2_rn(kv.z, kv.w)));
            *reinterpret_cast<uint2*>(&K16[key * 20 + 2 * c4]) = u;
            int d0 = c4 << 2;
            Vth[(d0    ) * 72 + key] = __float2half(vv.x);
            Vth[(d0 + 1) * 72 + key] = __float2half(vv.y);
            Vth[(d0 + 2) * 72 + key] = __float2half(vv.z);
            Vth[(d0 + 3) * 72 + key] = __float2half(vv.w);
        }
        if (tid < 64) {
            int j = j0 + tid;
            mk[tid] = (j >= nk) ? 2
                    : ((j < msplit) ? m1[(long)b * m1_bs + j]
                                    : m2[(long)b * m2_bs + j - msplit]);
        }
        __syncthreads();
        {
            float sacc[5][2][4];
            #pragma unroll
            for (int mf = 0; mf < 5; mf++)
                #pragma unroll
                for (int nf = 0; nf < 2; nf++)
                    #pragma unroll
                    for (int r = 0; r < 4; r++) sacc[mf][nf][r] = 0.f;
            #pragma unroll
            for (int ks = 0; ks < 2; ks++) {
                uint32_t af[5][4];
                #pragma unroll
                for (int mf = 0; mf < 5; mf++) {
                    const uint32_t* ap = &Q16[(mf * 16 + g) * 20 + ks * 8 + t4];
                    af[mf][0] = ap[0]; af[mf][1] = ap[8 * 20];
                    af[mf][2] = ap[4]; af[mf][3] = ap[8 * 20 + 4];
                }
                #pragma unroll
                for (int nf = 0; nf < 2; nf++) {
                    const uint32_t* wp = &K16[(wid * 16 + nf * 8 + g) * 20 + ks * 8 + t4];
                    uint32_t bf[2] = { wp[0], wp[4] };
                    #pragma unroll
                    for (int mf = 0; mf < 5; mf++) mma_f16(sacc[mf][nf], af[mf], bf);
                }
            }
            #pragma unroll
            for (int mf = 0; mf < 5; mf++) {
                #pragma unroll
                for (int nf = 0; nf < 2; nf++) {
                    int r0 = mf * 16 + g, col = wid * 16 + nf * 8 + 2 * t4;
                    Sf[r0 * 67 + col]       = sacc[mf][nf][0];
                    Sf[r0 * 67 + col + 1]   = sacc[mf][nf][1];
                    Sf[(r0+8) * 67 + col]   = sacc[mf][nf][2];
                    Sf[(r0+8) * 67 + col+1] = sacc[mf][nf][3];
                }
            }
        }
        __syncthreads();
        if (tid < 80) {
            float* srow = Sf + tid * 67;
            float cmax = -3.0e38f;
            for (int k = 0; k < 64; k++) {
                float sv = srow[k];
                unsigned char mv = mk[k];
                if (mv) sv = (mv == 1) ? -1e9f : -2e9f;
                srow[k] = sv;
                cmax = fmaxf(cmax, sv);
            }
            float newm = fmaxf(mrow, cmax);
            float f = __expf(mrow - newm);
            float sum = 0.f;
            uint32_t* prow = Pf + tid * 36;
            for (int k2 = 0; k2 < 32; k2++) {
                float p0 = __expf(srow[2*k2]   - newm);
                float p1 = __expf(srow[2*k2+1] - newm);
                sum += p0 + p1;
                prow[k2] = h2u(__floats2half2_rn(p0, p1));
            }
            lrow = lrow * f + sum;
            rowf[tid] = f;
            mrow = newm;
        }
        __syncthreads();
        #pragma unroll
        for (int mi = 0; mi < 2; mi++) {
            if (mi >= mfcnt) break;
            int rb = mrow0 + mi * 16;
            float f0 = rowf[rb + g], f1 = rowf[rb + 8 + g];
            #pragma unroll
            for (int nf = 0; nf < 4; nf++) {
                acc[mi][nf][0] *= f0; acc[mi][nf][1] *= f0;
                acc[mi][nf][2] *= f1; acc[mi][nf][3] *= f1;
            }
        }
        #pragma unroll
        for (int kf = 0; kf < 4; kf++) {
            uint32_t af[2][4];
            #pragma unroll
            for (int mi = 0; mi < 2; mi++) {
                if (mi >= mfcnt) break;
                const uint32_t* ap = &Pf[(mrow0 + mi * 16 + g) * 36 + kf * 8 + t4];
                af[mi][0] = ap[0]; af[mi][1] = ap[8 * 36];
                af[mi][2] = ap[4]; af[mi][3] = ap[8 * 36 + 4];
            }
            #pragma unroll
            for (int nf = 0; nf < 4; nf++) {
                const uint32_t* bp = &Vt[(nf * 8 + g) * 36 + kf * 8 + t4];
                uint32_t bf[2] = { bp[0], bp[4] };
                #pragma unroll
                for (int mi = 0; mi < 2; mi++) {
                    if (mi >= mfcnt) break;
                    mma_f16(acc[mi][nf], af[mi], bf);
                }
            }
        }
    }

    if (tid < 80) linv[tid] = 1.f / lrow;
    __syncthreads();

    #pragma unroll
    for (int mi = 0; mi < 2; mi++) {
        if (mi >= mfcnt) break;
        int rb = mrow0 + mi * 16;
        int r0 = rb + g, r1 = rb + 8 + g;
        float i0 = linv[r0], i1 = linv[r1];
        #pragma unroll
        for (int nf = 0; nf < 4; nf++) {
            int col = h * 32 + nf * 8 + 2 * t4;
            if (r0 < Tq)
                *reinterpret_cast<float2*>(O + ((long)b * Tq + r0) * Dm + col)
                    = make_float2(acc[mi][nf][0] * i0, acc[mi][nf][1] * i0);
            if (r1 < Tq)
                *reinterpret_cast<float2*>(O + ((long)b * Tq + r1) * Dm + col)
                    = make_float2(acc[mi][nf][2] * i1, acc[mi][nf][3] * i1);
        }
    }
}

// ---------------- residual + layernorm ----------------
__global__ void resid_ln(const float* __restrict__ X, const float* __restrict__ Y,
                         const float* __restrict__ Wb, const float* __restrict__ Bb,
                         const int* __restrict__ sid, float* __restrict__ Out)
{
    const int row = blockIdx.x;
    const int b = row / Tq;
    const int i = threadIdx.x;
    const int s = sid[b];
    float v = X[(long)row * Dm + i] + Y[(long)row * Dm + i];

    float sum = v, sq = v * v;
    #pragma unroll
    for (int off = 16; off > 0; off >>= 1) {
        sum += __shfl_xor_sync(0xffffffffu, sum, off);
        sq  += __shfl_xor_sync(0xffffffffu, sq,  off);
    }
    __shared__ float sS[8], sQ[8];
    if ((i & 31) == 0) { sS[i >> 5] = sum; sQ[i >> 5] = sq; }
    __syncthreads();
    float ts = 0.f, tq = 0.f;
    #pragma unroll
    for (int k = 0; k < 8; k++) { ts += sS[k]; tq += sQ[k]; }

    float mean = ts * (1.f / 256.f);
    float var  = tq * (1.f / 256.f) - mean * mean;
    float rstd = rsqrtf(var + 1e-5f);
    Out[(long)row * Dm + i] = (v - mean) * rstd * Wb[(long)s * Dm + i] + Bb[(long)s * Dm + i];
}

// ---------------------------------- launch ---------------------------------------------
extern "C" void kernel_launch(void* const* d_in, const int* in_sizes, int n_in,
                              void* d_out, int out_size)
{
    const float*         text  = (const float*)d_in[0];
    const unsigned char* tmask = (const unsigned char*)d_in[1];
    const float*         im1   = (const float*)d_in[2];
    const unsigned char* imk1  = (const unsigned char*)d_in[3];
    const float*         im2   = (const float*)d_in[4];
    const unsigned char* imk2  = (const unsigned char*)d_in[5];
    const int*           sid   = (const int*)d_in[6];
    const float* sa_in_w  = (const float*)d_in[7];
    const float* sa_in_b  = (const float*)d_in[8];
    const float* sa_out_w = (const float*)d_in[9];
    const float* sa_out_b = (const float*)d_in[10];
    const float* ca_in_w  = (const float*)d_in[11];
    const float* ca_in_b  = (const float*)d_in[12];
    const float* ca_out_w = (const float*)d_in[13];
    const float* ca_out_b = (const float*)d_in[14];
    const float* l1w = (const float*)d_in[15];
    const float* l1b = (const float*)d_in[16];
    const float* l2w = (const float*)d_in[17];
    const float* l2b = (const float*)d_in[18];
    const float* n1w = (const float*)d_in[19];
    const float* n1b = (const float*)d_in[20];
    const float* n2w = (const float*)d_in[21];
    const float* n2b = (const float*)d_in[22];
    const float* n3w = (const float*)d_in[23];
    const float* n3b = (const float*)d_in[24];
    float* out = (float*)d_out;

    static float *qkv=nullptr,*attn=nullptr,*proj=nullptr,*x1=nullptr,*x2=nullptr,
                 *caq=nullptr,*cakv=nullptr,*ffh=nullptr;
    static int *perm=nullptr;
    static cudaStream_t s2 = nullptr;
    static cudaEvent_t evFork = nullptr, evJoin = nullptr;
    if (!qkv) {
        cudaGetSymbolAddress((void**)&qkv,  g_qkv);
        cudaGetSymbolAddress((void**)&attn, g_attn);
        cudaGetSymbolAddress((void**)&proj, g_proj);
        cudaGetSymbolAddress((void**)&x1,   g_x1);
        cudaGetSymbolAddress((void**)&x2,   g_x2);
        cudaGetSymbolAddress((void**)&caq,  g_caq);
        cudaGetSymbolAddress((void**)&cakv, g_cakv);
        cudaGetSymbolAddress((void**)&ffh,  g_ffh);
        cudaGetSymbolAddress((void**)&perm, g_perm);
        cudaFuncSetAttribute(attn_tc, cudaFuncAttributeMaxDynamicSharedMemorySize, AO_SZ);
        cudaFuncSetAttribute(gemm_h<false>, cudaFuncAttributeMaxDynamicSharedMemorySize, GSM);
        cudaFuncSetAttribute(gemm_h<true>,  cudaFuncAttributeMaxDynamicSharedMemorySize, GSM);
        cudaStreamCreateWithFlags(&s2, cudaStreamNonBlocking);
        cudaEventCreateWithFlags(&evFork, cudaEventDisableTiming);
        cudaEventCreateWithFlags(&evJoin, cudaEventDisableTiming);
    }

    const int LNROWS = Bsz * Tq;

    // 0) sid-sorted batch permutation (before fork so both streams see it)
    sid_sort<<<1, 64>>>(sid, perm);

    // ---- fork: CA K/V projection concurrent with SA chain ----
    cudaEventRecord(evFork, 0);
    cudaStreamWaitEvent(s2, evFork, 0);

    // [s2] 6) CA key/value proj from concat(im1,im2)
    gemm_h<false><<<dim3(512/128, 7, Bsz), 256, GSM, s2>>>(
        im1, im2, 400, (long)400*Dm,
        ca_in_w, (long)768*Dm, 256, ca_in_b, 768, sid, perm,
        cakv, (long)Mem*512, Mem, 512, Dm);
    cudaEventRecord(evJoin, s2);

    // [main] 1) SA qkv projection
    gemm_h<false><<<dim3(768/128, 1, Bsz), 256, GSM>>>(
        text, text, Tq, (long)Tq*Dm,
        sa_in_w, (long)768*Dm, 0, sa_in_b, 768, sid, perm,
        qkv, (long)Tq*768, Tq, 768, Dm);

    // [main] 2) SA attention
    attn_tc<<<dim3(Hh, Bsz), 128, AO_SZ>>>(
        qkv,       768, (long)Tq*768,
        qkv + 256, 768, (long)Tq*768,
        qkv + 512, 768, (long)Tq*768,
        tmask, Tq, tmask, 0, Tq + 1,
        Tq, attn);

    // [main] 3) SA out proj
    gemm_h<false><<<dim3(Dm/128, 1, Bsz), 256, GSM>>>(
        attn, attn, Tq, (long)Tq*Dm,
        sa_out_w, (long)Dm*Dm, 0, sa_out_b, Dm, sid, perm,
        proj, (long)Tq*Dm, Tq, Dm, Dm);

    // [main] 4) residual + LN1 -> x1
    resid_ln<<<LNROWS, 256>>>(text, proj, n1w, n1b, sid, x1);

    // [main] 5) CA query proj
    gemm_h<false><<<dim3(Dm/128, 1, Bsz), 256, GSM>>>(
        x1, x1, Tq, (long)Tq*Dm,
        ca_in_w, (long)768*Dm, 0, ca_in_b, 768, sid, perm,
        caq, (long)Tq*Dm, Tq, Dm, Dm);

    // ---- join ----
    cudaStreamWaitEvent(0, evJoin, 0);

    // 7) CA attention
    attn_tc<<<dim3(Hh, Bsz), 128, AO_SZ>>>(
        caq,        Dm,  (long)Tq*Dm,
        cakv,       512, (long)Mem*512,
        cakv + 256, 512, (long)Mem*512,
        imk1, 400, imk2, 400, 400,
        Mem, attn);

    // 8) CA out proj
    gemm_h<false><<<dim3(Dm/128, 1, Bsz), 256, GSM>>>(
        attn, attn, Tq, (long)Tq*Dm,
        ca_out_w, (long)Dm*Dm, 0, ca_out_b, Dm, sid, perm,
        proj, (long)Tq*Dm, Tq, Dm, Dm);

    // 9) residual + LN2 -> x2
    resid_ln<<<LNROWS, 256>>>(x1, proj, n2w, n2b, sid, x2);

    // 10) FFN up + relu
    gemm_h<true><<<dim3(DFFm/128, 1, Bsz), 256, GSM>>>(
        x2, x2, Tq, (long)Tq*Dm,
        l1w, (long)DFFm*Dm, 0, l1b, DFFm, sid, perm,
        ffh, (long)Tq*DFFm, Tq, DFFm, Dm);

    // 11) FFN down
    gemm_h<false><<<dim3(Dm/128, 1, Bsz), 256, GSM>>>(
        ffh, ffh, Tq, (long)Tq*DFFm,
        l2w, (long)Dm*DFFm, 0, l2b, Dm, sid, perm,
        proj, (long)Tq*Dm, Tq, Dm, DFFm);

    // 12) residual + LN3 -> output
    resid_ln<<<LNROWS, 256>>>(x2, proj, n3w, n3b, sid, out);
}

// round 16
// speedup vs baseline: 1.3124x; 1.0510x over previous
#include <cuda_runtime.h>
#include <cuda_fp16.h>
#include <math.h>
#include <cstdint>

#define Bsz 64
#define Tq  77
#define Dm  256
#define Hh  8
#define DFFm 2048
#define Mem 800

// ---------------- scratch ----------------
__device__ float g_qkv [Bsz*Tq*768];
__device__ float g_attn[Bsz*Tq*Dm];
__device__ float g_proj[Bsz*Tq*Dm];
__device__ float g_x1  [Bsz*Tq*Dm];
__device__ float g_x2  [Bsz*Tq*Dm];
__device__ float g_caq [Bsz*Tq*Dm];
__device__ float g_cakv[Bsz*Mem*512];
__device__ float g_ffh [(size_t)Bsz*Tq*DFFm];

__device__ __forceinline__ void mma_f16(float* d, const uint32_t* a, const uint32_t* b) {
    asm volatile("mma.sync.aligned.m16n8k16.row.col.f32.f16.f16.f32 "
        "{%0,%1,%2,%3}, {%4,%5,%6,%7}, {%8,%9}, {%0,%1,%2,%3};"
        : "+f"(d[0]), "+f"(d[1]), "+f"(d[2]), "+f"(d[3])
        : "r"(a[0]), "r"(a[1]), "r"(a[2]), "r"(a[3]), "r"(b[0]), "r"(b[1]));
}
__device__ __forceinline__ uint32_t h2u(__half2 h) { return *reinterpret_cast<uint32_t*>(&h); }
__device__ __forceinline__ uint32_t su32(const void* p) {
    uint32_t a;
    asm("{ .reg .u64 t; cvta.to.shared.u64 t, %1; cvt.u32.u64 %0, t; }" : "=r"(a) : "l"(p));
    return a;
}
__device__ __forceinline__ void ldsm_x4(uint32_t* r, uint32_t addr) {
    asm volatile("ldmatrix.sync.aligned.m8n8.x4.shared.b16 {%0,%1,%2,%3}, [%4];"
        : "=r"(r[0]), "=r"(r[1]), "=r"(r[2]), "=r"(r[3]) : "r"(addr));
}
#define BAR_SYNC(id)   asm volatile("bar.sync %0, 512;"   :: "r"(id) : "memory")
#define BAR_ARRIVE(id) asm volatile("bar.arrive %0, 512;" :: "r"(id) : "memory")

// ======== warp-specialized fp16 mma GEMM ========
// CTA 128Mx128N, BK=64, double-buffered. 512 threads:
// warps 8..15 producers (LDG f32 -> cvt f16 -> STS), warps 0..7 consumers
// (ldmatrix + mma, warp tile 64x32, R10 mapping). Named-barrier handshake:
//   full[p]  = bar 1+p : producers arrive, consumers sync
//   empty[p] = bar 3+p : consumers arrive, producers sync
#define GPITCH 36
#define GBUF   (128 * GPITCH)
#define GSM    (2 * GBUF * 4 * 2)      // 73728 bytes

template<bool RELU>
__global__ void __launch_bounds__(512, 1) gemm_h(
    const float* __restrict__ A1, const float* __restrict__ A2, int msplit, long a_bs,
    const float* __restrict__ Wbank, long w_bs, int w_roff,
    const float* __restrict__ Bbank, long b_bs, const int* __restrict__ sid,
    float* __restrict__ C, long c_bs, int M, int Nn, int K)
{
    extern __shared__ uint32_t dyn[];
    uint32_t* Abuf = dyn;              // [2][128][GPITCH]
    uint32_t* Wbuf = dyn + 2 * GBUF;   // [2][128][GPITCH]

    const int tid = threadIdx.x, wid = tid >> 5, lane = tid & 31;
    const int b = blockIdx.z, s = sid[b];
    const int m0 = blockIdx.y * 128, n0 = blockIdx.x * 128;
    const float* W  = Wbank + (long)s * w_bs + (long)w_roff * K;
    const float* Bi = Bbank + (long)s * b_bs + w_roff;
    const int NC = K >> 6;

    if (wid >= 8) {
        // ---------------- producer ----------------
        const int pt = tid - 256;
        const int sr = pt >> 4, sc4 = pt & 15;
        float4 areg[8], wreg[8];
        for (int c = 0; c < NC; c++) {
            const int p = c & 1;
            if (c >= 2) BAR_SYNC(3 + p);
            const int k0 = c << 6;
            #pragma unroll
            for (int r = 0; r < 8; r++) {
                int rg = m0 + sr + r * 16;
                if (rg < M) {
                    const float* Ap = (rg < msplit)
                        ? (A1 + (long)b * a_bs + (long)rg * K)
                        : (A2 + (long)b * a_bs + (long)(rg - msplit) * K);
                    areg[r] = *reinterpret_cast<const float4*>(Ap + k0 + (sc4 << 2));
                } else areg[r] = make_float4(0.f, 0.f, 0.f, 0.f);
                wreg[r] = *reinterpret_cast<const float4*>(W + (long)(n0 + sr + r * 16) * K + k0 + (sc4 << 2));
            }
            #pragma unroll
            for (int r = 0; r < 8; r++) {
                int row = sr + r * 16;
                uint2 ua = make_uint2(h2u(__floats2half2_rn(areg[r].x, areg[r].y)),
                                      h2u(__floats2half2_rn(areg[r].z, areg[r].w)));
                *reinterpret_cast<uint2*>(&Abuf[(p * 128 + row) * GPITCH + 2 * sc4]) = ua;
                uint2 uw = make_uint2(h2u(__floats2half2_rn(wreg[r].x, wreg[r].y)),
                                      h2u(__floats2half2_rn(wreg[r].z, wreg[r].w)));
                *reinterpret_cast<uint2*>(&Wbuf[(p * 128 + row) * GPITCH + 2 * sc4]) = uw;
            }
            asm volatile("membar.cta;" ::: "memory");
            BAR_ARRIVE(1 + p);
        }
    } else {
        // ---------------- consumer ----------------
        const int wm = (wid >> 2) * 64, wn = (wid & 3) * 32;
        const int lr = lane >> 2, lc = lane & 3;
        const int la7 = lane & 7, la15 = lane & 15;
        const int acol = (lane >> 4) * 4;
        const int brow = (lane >> 4) * 8 + la7;
        const int bcol = ((lane >> 3) & 1) * 4;

        float acc[4][4][4];
        #pragma unroll
        for (int i = 0; i < 4; i++)
            #pragma unroll
            for (int j = 0; j < 4; j++)
                #pragma unroll
                for (int r = 0; r < 4; r++) acc[i][j][r] = 0.f;

        for (int c = 0; c < NC; c++) {
            const int p = c & 1;
            BAR_SYNC(1 + p);
            #pragma unroll
            for (int ks = 0; ks < 4; ks++) {
                uint32_t af[4][4], bf[8];
                #pragma unroll
                for (int mf = 0; mf < 4; mf++)
                    ldsm_x4(af[mf], su32(&Abuf[(p * 128 + wm + mf * 16 + la15) * GPITCH + ks * 8 + acol]));
                ldsm_x4(bf,     su32(&Wbuf[(p * 128 + wn      + brow) * GPITCH + ks * 8 + bcol]));
                ldsm_x4(bf + 4, su32(&Wbuf[(p * 128 + wn + 16 + brow) * GPITCH + ks * 8 + bcol]));
                #pragma unroll
                for (int mf = 0; mf < 4; mf++)
                    #pragma unroll
                    for (int nf = 0; nf < 4; nf++)
                        mma_f16(acc[mf][nf], af[mf], &bf[nf * 2]);
            }
            BAR_ARRIVE(3 + p);
        }

        #pragma unroll
        for (int mf = 0; mf < 4; mf++) {
            const int row = m0 + wm + mf * 16 + lr;
            #pragma unroll
            for (int nf = 0; nf < 4; nf++) {
                const int col = n0 + wn + nf * 8 + 2 * lc;
                float b0 = Bi[col], b1 = Bi[col + 1];
                if (row < M) {
                    float v0 = acc[mf][nf][0] + b0;
                    float v1 = acc[mf][nf][1] + b1;
                    if (RELU) { v0 = fmaxf(v0, 0.f); v1 = fmaxf(v1, 0.f); }
                    *reinterpret_cast<float2*>(C + (long)b * c_bs + (long)row * Nn + col) = make_float2(v0, v1);
                }
                if (row + 8 < M) {
                    float v2 = acc[mf][nf][2] + b0;
                    float v3 = acc[mf][nf][3] + b1;
                    if (RELU) { v2 = fmaxf(v2, 0.f); v3 = fmaxf(v3, 0.f); }
                    *reinterpret_cast<float2*>(C + (long)b * c_bs + (long)(row + 8) * Nn + col) = make_float2(v2, v3);
                }
            }
        }
    }
}

// ======== tensor-core flash attention (unchanged) ========
#define AO_Q   0
#define AO_K   6400
#define AO_V   11520
#define AO_P   16128
#define AO_S   27648
#define AO_F   49088
#define AO_L   49408
#define AO_M   49728
#define AO_SZ  49920

__global__ void __launch_bounds__(128) attn_tc(
    const float* __restrict__ Q, int q_rs, long q_bs,
    const float* __restrict__ Kp, int k_rs, long k_bs,
    const float* __restrict__ Vp, int v_rs, long v_bs,
    const unsigned char* __restrict__ m1, int m1_bs,
    const unsigned char* __restrict__ m2, int m2_bs, int msplit,
    int nk, float* __restrict__ O)
{
    extern __shared__ char sm[];
    uint32_t* Q16 = (uint32_t*)(sm + AO_Q);
    uint32_t* K16 = (uint32_t*)(sm + AO_K);
    uint32_t* Vt  = (uint32_t*)(sm + AO_V);
    __half*   Vth = (__half*)(sm + AO_V);
    uint32_t* Pf  = (uint32_t*)(sm + AO_P);
    float*    Sf  = (float*)(sm + AO_S);
    float*    rowf= (float*)(sm + AO_F);
    float*    linv= (float*)(sm + AO_L);
    unsigned char* mk = (unsigned char*)(sm + AO_M);

    const int h = blockIdx.x, b = blockIdx.y;
    const int tid = threadIdx.x, wid = tid >> 5;
    const int g = (tid & 31) >> 2, t4 = tid & 3;
    const float* Qb = Q  + (long)b * q_bs + h * 32;
    const float* Kb = Kp + (long)b * k_bs + h * 32;
    const float* Vb = Vp + (long)b * v_bs + h * 32;
    const int NCH = (nk + 63) >> 6;
    const float scl = 0.17677669529663687f;

    for (int i = tid; i < 80 * 8; i += 128) {
        int row = i >> 3, c4 = i & 7;
        float4 v = make_float4(0.f, 0.f, 0.f, 0.f);
        if (row < Tq) v = *reinterpret_cast<const float4*>(Qb + (long)row * q_rs + (c4 << 2));
        uint2 u = make_uint2(h2u(__floats2half2_rn(v.x * scl, v.y * scl)),
                             h2u(__floats2half2_rn(v.z * scl, v.w * scl)));
        *reinterpret_cast<uint2*>(&Q16[row * 20 + 2 * c4]) = u;
    }

    float mrow = -INFINITY, lrow = 0.f;
    const int mfcnt = (wid == 3) ? 2 : 1;
    const int mrow0 = wid * 16;
    float acc[2][4][4];
    #pragma unroll
    for (int i = 0; i < 2; i++)
        #pragma unroll
        for (int j = 0; j < 4; j++)
            #pragma unroll
            for (int r = 0; r < 4; r++) acc[i][j][r] = 0.f;

    for (int c = 0; c < NCH; c++) {
        const int j0 = c << 6;
        __syncthreads();
        for (int i = tid; i < 64 * 8; i += 128) {
            int key = i >> 3, c4 = i & 7;
            int j = j0 + key;
            float4 kv = make_float4(0.f, 0.f, 0.f, 0.f);
            float4 vv = make_float4(0.f, 0.f, 0.f, 0.f);
            if (j < nk) {
                kv = *reinterpret_cast<const float4*>(Kb + (long)j * k_rs + (c4 << 2));
                vv = *reinterpret_cast<const float4*>(Vb + (long)j * v_rs + (c4 << 2));
            }
            uint2 u = make_uint2(h2u(__floats2half2_rn(kv.x, kv.y)),
                                 h2u(__floats2half2_rn(kv.z, kv.w)));
            *reinterpret_cast<uint2*>(&K16[key * 20 + 2 * c4]) = u;
            int d0 = c4 << 2;
            Vth[(d0    ) * 72 + key] = __float2half(vv.x);
            Vth[(d0 + 1) * 72 + key] = __float2half(vv.y);
            Vth[(d0 + 2) * 72 + key] = __float2half(vv.z);
            Vth[(d0 + 3) * 72 + key] = __float2half(vv.w);
        }
        if (tid < 64) {
            int j = j0 + tid;
            mk[tid] = (j >= nk) ? 2
                    : ((j < msplit) ? m1[(long)b * m1_bs + j]
                                    : m2[(long)b * m2_bs + j - msplit]);
        }
        __syncthreads();
        {
            float sacc[5][2][4];
            #pragma unroll
            for (int mf = 0; mf < 5; mf++)
                #pragma unroll
                for (int nf = 0; nf < 2; nf++)
                    #pragma unroll
                    for (int r = 0; r < 4; r++) sacc[mf][nf][r] = 0.f;
            #pragma unroll
            for (int ks = 0; ks < 2; ks++) {
                uint32_t af[5][4];
                #pragma unroll
                for (int mf = 0; mf < 5; mf++) {
                    const uint32_t* ap = &Q16[(mf * 16 + g) * 20 + ks * 8 + t4];
                    af[mf][0] = ap[0]; af[mf][1] = ap[8 * 20];
                    af[mf][2] = ap[4]; af[mf][3] = ap[8 * 20 + 4];
                }
                #pragma unroll
                for (int nf = 0; nf < 2; nf++) {
                    const uint32_t* wp = &K16[(wid * 16 + nf * 8 + g) * 20 + ks * 8 + t4];
                    uint32_t bf[2] = { wp[0], wp[4] };
                    #pragma unroll
                    for (int mf = 0; mf < 5; mf++) mma_f16(sacc[mf][nf], af[mf], bf);
                }
            }
            #pragma unroll
            for (int mf = 0; mf < 5; mf++) {
                #pragma unroll
                for (int nf = 0; nf < 2; nf++) {
                    int r0 = mf * 16 + g, col = wid * 16 + nf * 8 + 2 * t4;
                    Sf[r0 * 67 + col]       = sacc[mf][nf][0];
                    Sf[r0 * 67 + col + 1]   = sacc[mf][nf][1];
                    Sf[(r0+8) * 67 + col]   = sacc[mf][nf][2];
                    Sf[(r0+8) * 67 + col+1] = sacc[mf][nf][3];
                }
            }
        }
        __syncthreads();
        if (tid < 80) {
            float* srow = Sf + tid * 67;
            float cmax = -3.0e38f;
            for (int k = 0; k < 64; k++) {
                float sv = srow[k];
                unsigned char mv = mk[k];
                if (mv) sv = (mv == 1) ? -1e9f : -2e9f;
                srow[k] = sv;
                cmax = fmaxf(cmax, sv);
            }
            float newm = fmaxf(mrow, cmax);
            float f = __expf(mrow - newm);
            float sum = 0.f;
            uint32_t* prow = Pf + tid * 36;
            for (int k2 = 0; k2 < 32; k2++) {
                float p0 = __expf(srow[2*k2]   - newm);
                float p1 = __expf(srow[2*k2+1] - newm);
                sum += p0 + p1;
                prow[k2] = h2u(__floats2half2_rn(p0, p1));
            }
            lrow = lrow * f + sum;
            rowf[tid] = f;
            mrow = newm;
        }
        __syncthreads();
        #pragma unroll
        for (int mi = 0; mi < 2; mi++) {
            if (mi >= mfcnt) break;
            int rb = mrow0 + mi * 16;
            float f0 = rowf[rb + g], f1 = rowf[rb + 8 + g];
            #pragma unroll
            for (int nf = 0; nf < 4; nf++) {
                acc[mi][nf][0] *= f0; acc[mi][nf][1] *= f0;
                acc[mi][nf][2] *= f1; acc[mi][nf][3] *= f1;
            }
        }
        #pragma unroll
        for (int kf = 0; kf < 4; kf++) {
            uint32_t af[2][4];
            #pragma unroll
            for (int mi = 0; mi < 2; mi++) {
                if (mi >= mfcnt) break;
                const uint32_t* ap = &Pf[(mrow0 + mi * 16 + g) * 36 + kf * 8 + t4];
                af[mi][0] = ap[0]; af[mi][1] = ap[8 * 36];
                af[mi][2] = ap[4]; af[mi][3] = ap[8 * 36 + 4];
            }
            #pragma unroll
            for (int nf = 0; nf < 4; nf++) {
                const uint32_t* bp = &Vt[(nf * 8 + g) * 36 + kf * 8 + t4];
                uint32_t bf[2] = { bp[0], bp[4] };
                #pragma unroll
                for (int mi = 0; mi < 2; mi++) {
                    if (mi >= mfcnt) break;
                    mma_f16(acc[mi][nf], af[mi], bf);
                }
            }
        }
    }

    if (tid < 80) linv[tid] = 1.f / lrow;
    __syncthreads();

    #pragma unroll
    for (int mi = 0; mi < 2; mi++) {
        if (mi >= mfcnt) break;
        int rb = mrow0 + mi * 16;
        int r0 = rb + g, r1 = rb + 8 + g;
        float i0 = linv[r0], i1 = linv[r1];
        #pragma unroll
        for (int nf = 0; nf < 4; nf++) {
            int col = h * 32 + nf * 8 + 2 * t4;
            if (r0 < Tq)
                *reinterpret_cast<float2*>(O + ((long)b * Tq + r0) * Dm + col)
                    = make_float2(acc[mi][nf][0] * i0, acc[mi][nf][1] * i0);
            if (r1 < Tq)
                *reinterpret_cast<float2*>(O + ((long)b * Tq + r1) * Dm + col)
                    = make_float2(acc[mi][nf][2] * i1, acc[mi][nf][3] * i1);
        }
    }
}

// ---------------- residual + layernorm ----------------
__global__ void resid_ln(const float* __restrict__ X, const float* __restrict__ Y,
                         const float* __restrict__ Wb, const float* __restrict__ Bb,
                         const int* __restrict__ sid, float* __restrict__ Out)
{
    const int row = blockIdx.x;
    const int b = row / Tq;
    const int i = threadIdx.x;
    const int s = sid[b];
    float v = X[(long)row * Dm + i] + Y[(long)row * Dm + i];

    float sum = v, sq = v * v;
    #pragma unroll
    for (int off = 16; off > 0; off >>= 1) {
        sum += __shfl_xor_sync(0xffffffffu, sum, off);
        sq  += __shfl_xor_sync(0xffffffffu, sq,  off);
    }
    __shared__ float sS[8], sQ[8];
    if ((i & 31) == 0) { sS[i >> 5] = sum; sQ[i >> 5] = sq; }
    __syncthreads();
    float ts = 0.f, tq = 0.f;
    #pragma unroll
    for (int k = 0; k < 8; k++) { ts += sS[k]; tq += sQ[k]; }

    float mean = ts * (1.f / 256.f);
    float var  = tq * (1.f / 256.f) - mean * mean;
    float rstd = rsqrtf(var + 1e-5f);
    Out[(long)row * Dm + i] = (v - mean) * rstd * Wb[(long)s * Dm + i] + Bb[(long)s * Dm + i];
}

// ---------------------------------- launch ---------------------------------------------
extern "C" void kernel_launch(void* const* d_in, const int* in_sizes, int n_in,
                              void* d_out, int out_size)
{
    const float*         text  = (const float*)d_in[0];
    const unsigned char* tmask = (const unsigned char*)d_in[1];
    const float*         im1   = (const float*)d_in[2];
    const unsigned char* imk1  = (const unsigned char*)d_in[3];
    const float*         im2   = (const float*)d_in[4];
    const unsigned char* imk2  = (const unsigned char*)d_in[5];
    const int*           sid   = (const int*)d_in[6];
    const float* sa_in_w  = (const float*)d_in[7];
    const float* sa_in_b  = (const float*)d_in[8];
    const float* sa_out_w = (const float*)d_in[9];
    const float* sa_out_b = (const float*)d_in[10];
    const float* ca_in_w  = (const float*)d_in[11];
    const float* ca_in_b  = (const float*)d_in[12];
    const float* ca_out_w = (const float*)d_in[13];
    const float* ca_out_b = (const float*)d_in[14];
    const float* l1w = (const float*)d_in[15];
    const float* l1b = (const float*)d_in[16];
    const float* l2w = (const float*)d_in[17];
    const float* l2b = (const float*)d_in[18];
    const float* n1w = (const float*)d_in[19];
    const float* n1b = (const float*)d_in[20];
    const float* n2w = (const float*)d_in[21];
    const float* n2b = (const float*)d_in[22];
    const float* n3w = (const float*)d_in[23];
    const float* n3b = (const float*)d_in[24];
    float* out = (float*)d_out;

    static float *qkv=nullptr,*attn=nullptr,*proj=nullptr,*x1=nullptr,*x2=nullptr,
                 *caq=nullptr,*cakv=nullptr,*ffh=nullptr;
    static cudaStream_t s2 = nullptr;
    static cudaEvent_t evFork = nullptr, evJoin = nullptr;
    if (!qkv) {
        cudaGetSymbolAddress((void**)&qkv,  g_qkv);
        cudaGetSymbolAddress((void**)&attn, g_attn);
        cudaGetSymbolAddress((void**)&proj, g_proj);
        cudaGetSymbolAddress((void**)&x1,   g_x1);
        cudaGetSymbolAddress((void**)&x2,   g_x2);
        cudaGetSymbolAddress((void**)&caq,  g_caq);
        cudaGetSymbolAddress((void**)&cakv, g_cakv);
        cudaGetSymbolAddress((void**)&ffh,  g_ffh);
        cudaFuncSetAttribute(attn_tc, cudaFuncAttributeMaxDynamicSharedMemorySize, AO_SZ);
        cudaFuncSetAttribute(gemm_h<false>, cudaFuncAttributeMaxDynamicSharedMemorySize, GSM);
        cudaFuncSetAttribute(gemm_h<true>,  cudaFuncAttributeMaxDynamicSharedMemorySize, GSM);
        cudaStreamCreateWithFlags(&s2, cudaStreamNonBlocking);
        cudaEventCreateWithFlags(&evFork, cudaEventDisableTiming);
        cudaEventCreateWithFlags(&evJoin, cudaEventDisableTiming);
    }

    const int LNROWS = Bsz * Tq;

    // ---- fork: CA K/V projection concurrent with SA chain ----
    cudaEventRecord(evFork, 0);
    cudaStreamWaitEvent(s2, evFork, 0);

    // [s2] 6) CA key/value proj from concat(im1,im2)
    gemm_h<false><<<dim3(512/128, 7, Bsz), 512, GSM, s2>>>(
        im1, im2, 400, (long)400*Dm,
        ca_in_w, (long)768*Dm, 256, ca_in_b, 768, sid,
        cakv, (long)Mem*512, Mem, 512, Dm);
    cudaEventRecord(evJoin, s2);

    // [main] 1) SA qkv projection
    gemm_h<false><<<dim3(768/128, 1, Bsz), 512, GSM>>>(
        text, text, Tq, (long)Tq*Dm,
        sa_in_w, (long)768*Dm, 0, sa_in_b, 768, sid,
        qkv, (long)Tq*768, Tq, 768, Dm);

    // [main] 2) SA attention
    attn_tc<<<dim3(Hh, Bsz), 128, AO_SZ>>>(
        qkv,       768, (long)Tq*768,
        qkv + 256, 768, (long)Tq*768,
        qkv + 512, 768, (long)Tq*768,
        tmask, Tq, tmask, 0, Tq + 1,
        Tq, attn);

    // [main] 3) SA out proj
    gemm_h<false><<<dim3(Dm/128, 1, Bsz), 512, GSM>>>(
        attn, attn, Tq, (long)Tq*Dm,
        sa_out_w, (long)Dm*Dm, 0, sa_out_b, Dm, sid,
        proj, (long)Tq*Dm, Tq, Dm, Dm);

    // [main] 4) residual + LN1 -> x1
    resid_ln<<<LNROWS, 256>>>(text, proj, n1w, n1b, sid, x1);

    // [main] 5) CA query proj
    gemm_h<false><<<dim3(Dm/128, 1, Bsz), 512, GSM>>>(
        x1, x1, Tq, (long)Tq*Dm,
        ca_in_w, (long)768*Dm, 0, ca_in_b, 768, sid,
        caq, (long)Tq*Dm, Tq, Dm, Dm);

    // ---- join ----
    cudaStreamWaitEvent(0, evJoin, 0);

    // 7) CA attention
    attn_tc<<<dim3(Hh, Bsz), 128, AO_SZ>>>(
        caq,        Dm,  (long)Tq*Dm,
        cakv,       512, (long)Mem*512,
        cakv + 256, 512, (long)Mem*512,
        imk1, 400, imk2, 400, 400,
        Mem, attn);

    // 8) CA out proj
    gemm_h<false><<<dim3(Dm/128, 1, Bsz), 512, GSM>>>(
        attn, attn, Tq, (long)Tq*Dm,
        ca_out_w, (long)Dm*Dm, 0, ca_out_b, Dm, sid,
        proj, (long)Tq*Dm, Tq, Dm, Dm);

    // 9) residual + LN2 -> x2
    resid_ln<<<LNROWS, 256>>>(x1, proj, n2w, n2b, sid, x2);

    // 10) FFN up + relu
    gemm_h<true><<<dim3(DFFm/128, 1, Bsz), 512, GSM>>>(
        x2, x2, Tq, (long)Tq*Dm,
        l1w, (long)DFFm*Dm, 0, l1b, DFFm, sid,
        ffh, (long)Tq*DFFm, Tq, DFFm, Dm);

    // 11) FFN down
    gemm_h<false><<<dim3(Dm/128, 1, Bsz), 512, GSM>>>(
        ffh, ffh, Tq, (long)Tq*DFFm,
        l2w, (long)Dm*DFFm, 0, l2b, Dm, sid,
        proj, (long)Tq*Dm, Tq, Dm, DFFm);

    // 12) residual + LN3 -> output
    resid_ln<<<LNROWS, 256>>>(x2, proj, n3w, n3b, sid, out);
}